// round 10
// baseline (speedup 1.0000x reference)
#include <cuda_runtime.h>

// FeedForwardQuantum — persistent grid-stride, warp-per-token, smem weights.
//   theta = dot(x_row, W1) + b1 ; out = cos(theta)*cos(phi) * W2 + b2
// EMBED_DIM=1024 (256 float4), tokens = 32768.
//
// R8 body (best: 39.3us kernel, 6.83 TB/s) made persistent: grid = SMs*8
// CTAs, each warp grid-strides over tokens. Removes 3.46 waves of CTA
// launch/drain churn and re-staging of the 12KB weight smem (once per CTA
// instead of once per 8 tokens). Everything else identical: <=32-reg
// batching (2x4 float4 front-batched __ldcs), shuffle-only reduction,
// __stcs streaming stores.

#define EMBED_F4       256   // float4s per token row
#define WARPS_PER_CTA    8
#define THREADS        (WARPS_PER_CTA * 32)

__global__ __launch_bounds__(THREADS, 8)
void ffq_kernel(const float4* __restrict__ x,
                const float4* __restrict__ W1,
                const float*  __restrict__ b1,
                const float*  __restrict__ phi,
                const float4* __restrict__ W2,
                const float4* __restrict__ b2,
                float4* __restrict__ out,
                int tokens)
{
    __shared__ float4 sW1[EMBED_F4];
    __shared__ float4 sW2[EMBED_F4];
    __shared__ float4 sB2[EMBED_F4];

    const int tid = threadIdx.x;
    sW1[tid] = W1[tid];          // staged once per (persistent) CTA
    sW2[tid] = W2[tid];
    sB2[tid] = b2[tid];
    __syncthreads();

    const int warp = tid >> 5;
    const int lane = tid & 31;
    const int warpGlobal = blockIdx.x * WARPS_PER_CTA + warp;
    const int totalWarps = gridDim.x * WARPS_PER_CTA;

    const float bias1 = b1[0];
    const float cphi  = __cosf(phi[0]);

    for (int token = warpGlobal; token < tokens; token += totalWarps) {
        const long rbase = (long)token * EMBED_F4 + lane;

        float p = 0.0f;
        // Batch 1: 4 front-batched streaming loads, consume vs smem W1.
        {
            float4 xv[4];
            #pragma unroll
            for (int i = 0; i < 4; i++)
                xv[i] = __ldcs(&x[rbase + 32 * i]);
            #pragma unroll
            for (int i = 0; i < 4; i++) {
                const float4 wv = sW1[lane + 32 * i];
                p = fmaf(xv[i].x, wv.x,
                    fmaf(xv[i].y, wv.y,
                    fmaf(xv[i].z, wv.z,
                    fmaf(xv[i].w, wv.w, p))));
            }
        }
        // Batch 2.
        {
            float4 xv[4];
            #pragma unroll
            for (int i = 0; i < 4; i++)
                xv[i] = __ldcs(&x[rbase + 32 * (i + 4)]);
            #pragma unroll
            for (int i = 0; i < 4; i++) {
                const float4 wv = sW1[lane + 32 * (i + 4)];
                p = fmaf(xv[i].x, wv.x,
                    fmaf(xv[i].y, wv.y,
                    fmaf(xv[i].z, wv.z,
                    fmaf(xv[i].w, wv.w, p))));
            }
        }

        // Warp-only reduction.
        #pragma unroll
        for (int o = 16; o > 0; o >>= 1)
            p += __shfl_xor_sync(0xffffffffu, p, o);

        const float q = __cosf(p + bias1) * cphi;

        // out = q * W2 + b2 from smem; streaming stores.
        #pragma unroll
        for (int i = 0; i < 8; i++) {
            const float4 w2 = sW2[lane + 32 * i];
            const float4 bb = sB2[lane + 32 * i];
            float4 o;
            o.x = fmaf(q, w2.x, bb.x);
            o.y = fmaf(q, w2.y, bb.y);
            o.z = fmaf(q, w2.z, bb.z);
            o.w = fmaf(q, w2.w, bb.w);
            __stcs(&out[rbase + 32 * i], o);
        }
    }
}

extern "C" void kernel_launch(void* const* d_in, const int* in_sizes, int n_in,
                              void* d_out, int out_size)
{
    const float4* x   = (const float4*)d_in[0];
    const float4* W1  = (const float4*)d_in[1];
    const float*  b1  = (const float*) d_in[2];
    const float*  phi = (const float*) d_in[3];
    const float4* W2  = (const float4*)d_in[4];
    const float4* b2  = (const float4*)d_in[5];
    float4* out = (float4*)d_out;

    const int tokens = in_sizes[0] / (EMBED_F4 * 4);   // 32768

    int sms = 148;
    cudaDeviceGetAttribute(&sms, cudaDevAttrMultiProcessorCount, 0);
    int ctas = sms * 8;                                 // one full resident wave
    if (ctas > tokens / WARPS_PER_CTA) ctas = tokens / WARPS_PER_CTA;

    ffq_kernel<<<ctas, THREADS>>>(x, W1, b1, phi, W2, b2, out, tokens);
}

// round 12
// speedup vs baseline: 1.0846x; 1.0846x over previous
#include <cuda_runtime.h>
#include <cstdint>

// FeedForwardQuantum — R8 structure + 256-bit (v8) global accesses.
//   theta = dot(x_row, W1) + b1 ; out = cos(theta)*cos(phi) * W2 + b2
// EMBED_DIM=1024 (= 128 v8-chunks of 8 floats), tokens = 32768.
//
// R8 (39.3us, 6.83 TB/s) with the one untested lever: sm_10x 256-bit
// vector ld/st. Halves global memory instructions per token (16 -> 8),
// doubling bytes per L1tex queue entry / LSU issue slot. Warp-per-token,
// grid 4096 (waves pipeline fine — persistence measured WORSE), smem
// weights, shuffle-only reduction, streaming (.cs) policy on both paths.

#define EMBED_F4       256   // float4s per token row
#define WARPS_PER_CTA    8
#define THREADS        (WARPS_PER_CTA * 32)

__device__ __forceinline__ void ldg256_cs(uint32_t r[8], const void* p) {
    asm volatile(
        "ld.global.cs.v8.b32 {%0,%1,%2,%3,%4,%5,%6,%7}, [%8];"
        : "=r"(r[0]), "=r"(r[1]), "=r"(r[2]), "=r"(r[3]),
          "=r"(r[4]), "=r"(r[5]), "=r"(r[6]), "=r"(r[7])
        : "l"(p));
}

__device__ __forceinline__ void stg256_cs(void* p, const uint32_t r[8]) {
    asm volatile(
        "st.global.cs.v8.b32 [%0], {%1,%2,%3,%4,%5,%6,%7,%8};"
        :: "l"(p),
           "r"(r[0]), "r"(r[1]), "r"(r[2]), "r"(r[3]),
           "r"(r[4]), "r"(r[5]), "r"(r[6]), "r"(r[7])
        : "memory");
}

__global__ __launch_bounds__(THREADS, 8)
void ffq_kernel(const float* __restrict__ x,
                const float4* __restrict__ W1,
                const float*  __restrict__ b1,
                const float*  __restrict__ phi,
                const float4* __restrict__ W2,
                const float4* __restrict__ b2,
                float* __restrict__ out)
{
    __shared__ float4 sW1[EMBED_F4];
    __shared__ float4 sW2[EMBED_F4];
    __shared__ float4 sB2[EMBED_F4];

    const int tid = threadIdx.x;
    sW1[tid] = W1[tid];
    sW2[tid] = W2[tid];
    sB2[tid] = b2[tid];
    __syncthreads();

    const int warp = tid >> 5;
    const int lane = tid & 31;
    const long token = (long)blockIdx.x * WARPS_PER_CTA + warp;
    // thread's base float offset within its token row for chunk j:
    //   j*256 + lane*8   (warp access = 1024B contiguous, fully coalesced)
    const float* xrow = x   + token * 1024 + lane * 8;
    float*       orow = out + token * 1024 + lane * 8;

    float p = 0.0f;

    // 4 v8 loads in 2 front-batched pairs (16 regs per pair, total <=32).
    #pragma unroll
    for (int half = 0; half < 2; half++) {
        uint32_t xv0[8], xv1[8];
        ldg256_cs(xv0, xrow + (2 * half + 0) * 256);
        ldg256_cs(xv1, xrow + (2 * half + 1) * 256);

        #pragma unroll
        for (int j = 0; j < 2; j++) {
            const uint32_t* xv = j ? xv1 : xv0;
            const int f4base = (2 * half + j) * 64 + lane * 2;  // float4 index
            #pragma unroll
            for (int k = 0; k < 2; k++) {
                const float4 wv = sW1[f4base + k];
                p = fmaf(__uint_as_float(xv[4 * k + 0]), wv.x,
                    fmaf(__uint_as_float(xv[4 * k + 1]), wv.y,
                    fmaf(__uint_as_float(xv[4 * k + 2]), wv.z,
                    fmaf(__uint_as_float(xv[4 * k + 3]), wv.w, p))));
            }
        }
    }

    // Warp-only reduction.
    #pragma unroll
    for (int o = 16; o > 0; o >>= 1)
        p += __shfl_xor_sync(0xffffffffu, p, o);

    const float q = __cosf(p + b1[0]) * __cosf(phi[0]);

    // 4 v8 streaming stores of q * W2 + b2.
    #pragma unroll
    for (int j = 0; j < 4; j++) {
        const int f4base = j * 64 + lane * 2;
        uint32_t ov[8];
        #pragma unroll
        for (int k = 0; k < 2; k++) {
            const float4 w2 = sW2[f4base + k];
            const float4 bb = sB2[f4base + k];
            ov[4 * k + 0] = __float_as_uint(fmaf(q, w2.x, bb.x));
            ov[4 * k + 1] = __float_as_uint(fmaf(q, w2.y, bb.y));
            ov[4 * k + 2] = __float_as_uint(fmaf(q, w2.z, bb.z));
            ov[4 * k + 3] = __float_as_uint(fmaf(q, w2.w, bb.w));
        }
        stg256_cs(orow + j * 256, ov);
    }
}

extern "C" void kernel_launch(void* const* d_in, const int* in_sizes, int n_in,
                              void* d_out, int out_size)
{
    const float*  x   = (const float*) d_in[0];
    const float4* W1  = (const float4*)d_in[1];
    const float*  b1  = (const float*) d_in[2];
    const float*  phi = (const float*) d_in[3];
    const float4* W2  = (const float4*)d_in[4];
    const float4* b2  = (const float4*)d_in[5];
    float* out = (float*)d_out;

    const int tokens = in_sizes[0] / 1024;   // 32768
    ffq_kernel<<<tokens / WARPS_PER_CTA, THREADS>>>(x, W1, b1, phi, W2, b2, out);
}

// round 14
// speedup vs baseline: 1.0914x; 1.0063x over previous
#include <cuda_runtime.h>

// FeedForwardQuantum — final: fused warp-per-token + smem weights (R8 body).
//   theta = dot(x_row, W1) + b1 ; out = cos(theta)*cos(phi) * W2 + b2
// EMBED_DIM=1024 (256 float4), tokens = 32768.
//
// Measured landscape (kernel time): block-per-token 43.4us, warp-per-token
// 40.7, +occ8 39.9, +smem weights 39.3 (BEST), persistent 42.0, v8 ld/st
// 41.6, two-phase split 49.6. Pure-read and pure-write streams each measure
// BELOW the fused bidirectional 6.83 TB/s -> this kernel sits at the
// simultaneous read+write HBM ceiling (~85% of 8 TB/s spec).
// This revision = R8 + scalar loads (b1, phi) hoisted off the per-token
// critical path.

#define EMBED_F4       256   // float4s per token row
#define WARPS_PER_CTA    8
#define THREADS        (WARPS_PER_CTA * 32)

__global__ __launch_bounds__(THREADS, 8)
void ffq_kernel(const float4* __restrict__ x,
                const float4* __restrict__ W1,
                const float*  __restrict__ b1,
                const float*  __restrict__ phi,
                const float4* __restrict__ W2,
                const float4* __restrict__ b2,
                float4* __restrict__ out)
{
    __shared__ float4 sW1[EMBED_F4];
    __shared__ float4 sW2[EMBED_F4];
    __shared__ float4 sB2[EMBED_F4];

    const int tid = threadIdx.x;
    sW1[tid] = W1[tid];          // 256 threads x 1 float4 each, once per CTA
    sW2[tid] = W2[tid];
    sB2[tid] = b2[tid];

    // Hoist scalars before the streaming section (off the token critical path).
    const float bias1 = b1[0];
    const float cphi  = __cosf(phi[0]);
    __syncthreads();

    const int warp = tid >> 5;
    const int lane = tid & 31;
    const long token = (long)blockIdx.x * WARPS_PER_CTA + warp;
    const long rbase = token * EMBED_F4 + lane;

    float p = bias1;   // fold b1 into the reduction seed (lane 0's term x32... no:)
    // NOTE: bias must be added once, not per-lane — seed with bias1/32 would
    // lose precision; instead seed 0 and add after reduction.
    p = 0.0f;

    // Batch 1: 4 front-batched streaming loads, consume vs smem W1.
    {
        float4 xv[4];
        #pragma unroll
        for (int i = 0; i < 4; i++)
            xv[i] = __ldcs(&x[rbase + 32 * i]);
        #pragma unroll
        for (int i = 0; i < 4; i++) {
            const float4 wv = sW1[lane + 32 * i];
            p = fmaf(xv[i].x, wv.x,
                fmaf(xv[i].y, wv.y,
                fmaf(xv[i].z, wv.z,
                fmaf(xv[i].w, wv.w, p))));
        }
    }
    // Batch 2.
    {
        float4 xv[4];
        #pragma unroll
        for (int i = 0; i < 4; i++)
            xv[i] = __ldcs(&x[rbase + 32 * (i + 4)]);
        #pragma unroll
        for (int i = 0; i < 4; i++) {
            const float4 wv = sW1[lane + 32 * (i + 4)];
            p = fmaf(xv[i].x, wv.x,
                fmaf(xv[i].y, wv.y,
                fmaf(xv[i].z, wv.z,
                fmaf(xv[i].w, wv.w, p))));
        }
    }

    // Warp-only reduction.
    #pragma unroll
    for (int o = 16; o > 0; o >>= 1)
        p += __shfl_xor_sync(0xffffffffu, p, o);

    const float q = __cosf(p + bias1) * cphi;

    // out = q * W2 + b2 from smem; streaming stores.
    #pragma unroll
    for (int i = 0; i < 8; i++) {
        const float4 w2 = sW2[lane + 32 * i];
        const float4 bb = sB2[lane + 32 * i];
        float4 o;
        o.x = fmaf(q, w2.x, bb.x);
        o.y = fmaf(q, w2.y, bb.y);
        o.z = fmaf(q, w2.z, bb.z);
        o.w = fmaf(q, w2.w, bb.w);
        __stcs(&out[rbase + 32 * i], o);
    }
}

extern "C" void kernel_launch(void* const* d_in, const int* in_sizes, int n_in,
                              void* d_out, int out_size)
{
    const float4* x   = (const float4*)d_in[0];
    const float4* W1  = (const float4*)d_in[1];
    const float*  b1  = (const float*) d_in[2];
    const float*  phi = (const float*) d_in[3];
    const float4* W2  = (const float4*)d_in[4];
    const float4* b2  = (const float4*)d_in[5];
    float4* out = (float4*)d_out;

    const int tokens = in_sizes[0] / (EMBED_F4 * 4);   // 32768
    ffq_kernel<<<tokens / WARPS_PER_CTA, THREADS>>>(x, W1, b1, phi, W2, b2, out);
}

// round 16
// speedup vs baseline: 1.0937x; 1.0021x over previous
#include <cuda_runtime.h>

// FeedForwardQuantum — converged: warp-per-token, L1-resident weights (R5).
//   theta = dot(x_row, W1) + b1 ; out = cos(theta)*cos(phi) * W2 + b2
// EMBED_DIM=1024 (256 float4), tokens = 32768.
//
// Measured landscape (bench dur_us / ncu kernel us):
//   block-per-token        48.6 / 43.4
//   warp-per-token occ8    44.7 / 39.9   <- BEST bench (this kernel)
//   + smem weights         45.8 / 39.3
//   + smem + hoist         45.5 / 40.6
//   persistent grid-stride 49.7 / 42.0
//   v8 256-bit ld/st       45.8 / 41.6
//   two-phase split        49.6 / (21.2 store phase alone = 6.0 TB/s)
// Combined L2 traffic = 6.8 TB/s ~= the path-independent LTS cap
// (~6300 B/cyc full-chip); pure-read and pure-write streams each measure
// SLOWER than this fused bidirectional stream. Structural ceiling reached.
//
// Delta vs R5: b1/phi scalar loads hoisted ahead of the x streaming loads
// (off the per-token dependency chain). Everything else identical.
// (R15 was an infra failure — this is the R14 source resubmitted unchanged.)

#define EMBED_F4       256   // float4s per token row
#define WARPS_PER_CTA    8
#define THREADS        (WARPS_PER_CTA * 32)

__global__ __launch_bounds__(THREADS, 8)
void ffq_kernel(const float4* __restrict__ x,
                const float4* __restrict__ W1,
                const float*  __restrict__ b1,
                const float*  __restrict__ phi,
                const float4* __restrict__ W2,
                const float4* __restrict__ b2,
                float4* __restrict__ out)
{
    const int warp = threadIdx.x >> 5;
    const int lane = threadIdx.x & 31;
    const long token = (long)blockIdx.x * WARPS_PER_CTA + warp;
    const long rbase = token * EMBED_F4 + lane;

    // Scalars first: issued before the streaming section, L1-hit, off the
    // critical path by the time the reduction needs them.
    const float bias1 = b1[0];
    const float cphi  = __cosf(phi[0]);

    float p = 0.0f;

    // Batch 1: 4 front-batched streaming loads, then consume vs L1-resident W1.
    {
        float4 xv[4];
        #pragma unroll
        for (int i = 0; i < 4; i++)
            xv[i] = __ldcs(&x[rbase + 32 * i]);
        #pragma unroll
        for (int i = 0; i < 4; i++) {
            const float4 wv = W1[lane + 32 * i];   // 4KiB, L1-resident
            p = fmaf(xv[i].x, wv.x,
                fmaf(xv[i].y, wv.y,
                fmaf(xv[i].z, wv.z,
                fmaf(xv[i].w, wv.w, p))));
        }
    }
    // Batch 2.
    {
        float4 xv[4];
        #pragma unroll
        for (int i = 0; i < 4; i++)
            xv[i] = __ldcs(&x[rbase + 32 * (i + 4)]);
        #pragma unroll
        for (int i = 0; i < 4; i++) {
            const float4 wv = W1[lane + 32 * (i + 4)];
            p = fmaf(xv[i].x, wv.x,
                fmaf(xv[i].y, wv.y,
                fmaf(xv[i].z, wv.z,
                fmaf(xv[i].w, wv.w, p))));
        }
    }

    // Warp-only reduction: no smem, no block barrier.
    #pragma unroll
    for (int o = 16; o > 0; o >>= 1)
        p += __shfl_xor_sync(0xffffffffu, p, o);

    const float q = __cosf(p + bias1) * cphi;

    // out = q * W2 + b2  (W2/b2 L1-resident), streaming stores.
    #pragma unroll
    for (int i = 0; i < 8; i++) {
        const float4 w2 = W2[lane + 32 * i];
        const float4 bb = b2[lane + 32 * i];
        float4 o;
        o.x = fmaf(q, w2.x, bb.x);
        o.y = fmaf(q, w2.y, bb.y);
        o.z = fmaf(q, w2.z, bb.z);
        o.w = fmaf(q, w2.w, bb.w);
        __stcs(&out[rbase + 32 * i], o);
    }
}

extern "C" void kernel_launch(void* const* d_in, const int* in_sizes, int n_in,
                              void* d_out, int out_size)
{
    const float4* x   = (const float4*)d_in[0];
    const float4* W1  = (const float4*)d_in[1];
    const float*  b1  = (const float*) d_in[2];
    const float*  phi = (const float*) d_in[3];
    const float4* W2  = (const float4*)d_in[4];
    const float4* b2  = (const float4*)d_in[5];
    float4* out = (float4*)d_out;

    const int tokens = in_sizes[0] / (EMBED_F4 * 4);   // 32768
    ffq_kernel<<<tokens / WARPS_PER_CTA, THREADS>>>(x, W1, b1, phi, W2, b2, out);
}

// round 17
// speedup vs baseline: 1.1141x; 1.0187x over previous
#include <cuda_runtime.h>

// FeedForwardQuantum — warp-per-token, 128-thread CTAs (tail-granularity test).
//   theta = dot(x_row, W1) + b1 ; out = cos(theta)*cos(phi) * W2 + b2
// EMBED_DIM=1024 (256 float4), tokens = 32768.
//
// Same per-warp body as the converged R5/R16 kernel (reproducible at
// ~45.4us bench / ~40.2us kernel, = the ~6.8 TB/s fused-stream LTS/HBM
// ceiling). Single change: CTA = 4 warps, grid = 8192. Finer scheduling
// granularity -> smaller last-wave tail and smoother die-balancing; no
// smem/barriers so nothing is duplicated by the doubled CTA count.

#define EMBED_F4       256   // float4s per token row
#define WARPS_PER_CTA    4
#define THREADS        (WARPS_PER_CTA * 32)

__global__ __launch_bounds__(THREADS, 12)
void ffq_kernel(const float4* __restrict__ x,
                const float4* __restrict__ W1,
                const float*  __restrict__ b1,
                const float*  __restrict__ phi,
                const float4* __restrict__ W2,
                const float4* __restrict__ b2,
                float4* __restrict__ out)
{
    const int warp = threadIdx.x >> 5;
    const int lane = threadIdx.x & 31;
    const long token = (long)blockIdx.x * WARPS_PER_CTA + warp;
    const long rbase = token * EMBED_F4 + lane;

    // Scalars first: L1-hit, resolved well before the reduction needs them.
    const float bias1 = b1[0];
    const float cphi  = __cosf(phi[0]);

    float p = 0.0f;

    // Batch 1: 4 front-batched streaming loads, consume vs L1-resident W1.
    {
        float4 xv[4];
        #pragma unroll
        for (int i = 0; i < 4; i++)
            xv[i] = __ldcs(&x[rbase + 32 * i]);
        #pragma unroll
        for (int i = 0; i < 4; i++) {
            const float4 wv = W1[lane + 32 * i];   // 4KiB, L1-resident
            p = fmaf(xv[i].x, wv.x,
                fmaf(xv[i].y, wv.y,
                fmaf(xv[i].z, wv.z,
                fmaf(xv[i].w, wv.w, p))));
        }
    }
    // Batch 2.
    {
        float4 xv[4];
        #pragma unroll
        for (int i = 0; i < 4; i++)
            xv[i] = __ldcs(&x[rbase + 32 * (i + 4)]);
        #pragma unroll
        for (int i = 0; i < 4; i++) {
            const float4 wv = W1[lane + 32 * (i + 4)];
            p = fmaf(xv[i].x, wv.x,
                fmaf(xv[i].y, wv.y,
                fmaf(xv[i].z, wv.z,
                fmaf(xv[i].w, wv.w, p))));
        }
    }

    // Warp-only reduction: no smem, no block barrier.
    #pragma unroll
    for (int o = 16; o > 0; o >>= 1)
        p += __shfl_xor_sync(0xffffffffu, p, o);

    const float q = __cosf(p + bias1) * cphi;

    // out = q * W2 + b2  (W2/b2 L1-resident), streaming stores.
    #pragma unroll
    for (int i = 0; i < 8; i++) {
        const float4 w2 = W2[lane + 32 * i];
        const float4 bb = b2[lane + 32 * i];
        float4 o;
        o.x = fmaf(q, w2.x, bb.x);
        o.y = fmaf(q, w2.y, bb.y);
        o.z = fmaf(q, w2.z, bb.z);
        o.w = fmaf(q, w2.w, bb.w);
        __stcs(&out[rbase + 32 * i], o);
    }
}

extern "C" void kernel_launch(void* const* d_in, const int* in_sizes, int n_in,
                              void* d_out, int out_size)
{
    const float4* x   = (const float4*)d_in[0];
    const float4* W1  = (const float4*)d_in[1];
    const float*  b1  = (const float*) d_in[2];
    const float*  phi = (const float*) d_in[3];
    const float4* W2  = (const float4*)d_in[4];
    const float4* b2  = (const float4*)d_in[5];
    float4* out = (float4*)d_out;

    const int tokens = in_sizes[0] / (EMBED_F4 * 4);   // 32768
    ffq_kernel<<<tokens / WARPS_PER_CTA, THREADS>>>(x, W1, b1, phi, W2, b2, out);
}